// round 5
// baseline (speedup 1.0000x reference)
#include <cuda_runtime.h>

// SetEmbed: out[b] = (sum_{s<n_b} relu(X[b,s]@W1 + b1)) @ W2 + n_b*b2, then @ W3 + b3.
// Tile-parallel: one CTA per (batch, 128-row tile); partial pooled16 -> scratch;
// tiny epilogue kernel finishes W2/W3. Hot loop: k-per-lane, register-resident W1,
// packed f32x2 FMAs, x broadcast from smem (2 rows per warp -> bank-disjoint LDS.128).

#define B_      2048
#define S_      512
#define NFT     64
#define K1      16
#define K2      12
#define NOUT    32
#define TSR     128     // rows per CTA tile
#define NTILES  (S_ / TSR)   // 4
#define RSTRIDE 17      // float4 per smem row (68 floats)
#define NTHREADS 128

__device__ float g_scratch[B_ * NTILES * K1];   // [b][tile][k] partial pooled sums

__device__ __forceinline__ unsigned long long pack2(float lo, float hi) {
    unsigned long long r;
    asm("mov.b64 %0, {%1, %2};" : "=l"(r) : "f"(lo), "f"(hi));
    return r;
}
__device__ __forceinline__ void unpack2(unsigned long long v, float& lo, float& hi) {
    asm("mov.b64 {%0, %1}, %2;" : "=f"(lo), "=f"(hi) : "l"(v));
}
// d = a*b + d (two independent fp32 FMAs, one instruction)
__device__ __forceinline__ void ffma2(unsigned long long& d, unsigned long long a,
                                      unsigned long long b) {
    asm("fma.rn.f32x2 %0, %1, %2, %3;" : "=l"(d) : "l"(a), "l"(b), "l"(d));
}
__device__ __forceinline__ unsigned smem_u32(const void* p) {
    return (unsigned)__cvta_generic_to_shared(p);
}

__global__ __launch_bounds__(NTHREADS) void setembed_main(
    const float* __restrict__ X, const int* __restrict__ setSizes,
    const float* __restrict__ W1, const float* __restrict__ b1)
{
    __shared__ __align__(16) float4 Xs[TSR * RSTRIDE];   // 34816 B
    __shared__ float red[8][K1 + 1];

    const int bid  = blockIdx.x;
    const int b    = bid >> 2;
    const int tile = bid & 3;
    const int t    = threadIdx.x;
    const int n    = setSizes[b];
    const int base = tile * TSR;

    float* myScratch = &g_scratch[(b * NTILES + tile) * K1];
    if (base >= n) {                 // inactive tile: contribute exact zeros
        if (t < K1) myScratch[t] = 0.f;
        return;
    }
    const int cnt = min(TSR, n - base);

    // Stage cnt rows, coalesced float4 cp.async into padded smem rows.
    {
        const float4* Xg = reinterpret_cast<const float4*>(
            X + (size_t)b * S_ * NFT) + (size_t)base * 16;
#pragma unroll
        for (int m = 0; m < 16; m++) {
            int idx = t + m * NTHREADS;      // 0..2047 float4 slots
            int r = idx >> 4, c = idx & 15;
            if (r < cnt) {
                unsigned da = smem_u32(&Xs[r * RSTRIDE + c]);
                const float4* sa = &Xg[r * 16 + c];
                asm volatile("cp.async.cg.shared.global [%0], [%1], 16;"
                             :: "r"(da), "l"(sa));
            }
        }
        asm volatile("cp.async.commit_group;");
    }

    // W1 column k register-resident as 32 packed feature-pairs.
    const int k    = t & 15;
    const int slot = t >> 4;
    const int warp = t >> 5;
    const int half = (t >> 4) & 1;
    unsigned long long w1r[NFT / 2];
#pragma unroll
    for (int j = 0; j < NFT / 2; j++)
        w1r[j] = pack2(W1[(2 * j) * K1 + k], W1[(2 * j + 1) * K1 + k]);
    const float b1k = b1[k];

    asm volatile("cp.async.wait_group 0;");
    __syncthreads();

    float acc = 0.f;
#pragma unroll
    for (int pass = 0; pass < TSR / 8; pass++) {        // 16 passes, 2 rows/warp each
        const int r0 = pass * 8 + warp * 2;             // warp-uniform first row
        if (r0 < cnt) {
            const int r = r0 + half;
            const ulonglong2* xr =
                reinterpret_cast<const ulonglong2*>(&Xs[r * RSTRIDE]);
            unsigned long long h2a = 0ull, h2b = 0ull;
#pragma unroll
            for (int j4 = 0; j4 < 16; j4++) {
                ulonglong2 q = xr[j4];                  // LDS.128: 4 features
                ffma2(h2a, q.x, w1r[2 * j4]);           // weights from registers
                ffma2(h2b, q.y, w1r[2 * j4 + 1]);
            }
            float a0, a1, c0, c1;
            unpack2(h2a, a0, a1);
            unpack2(h2b, c0, c1);
            float s = (a0 + a1) + (c0 + c1) + b1k;
            if (r < cnt) acc += fmaxf(s, 0.f);          // relu, tail-masked
        }
    }

    // Reduce acc over the 8 row-slots per k, write partial to scratch.
    red[slot][k] = acc;
    __syncthreads();
    if (t < K1) {
        float s = 0.f;
#pragma unroll
        for (int ss = 0; ss < 8; ss++) s += red[ss][t];
        myScratch[t] = s;
    }
}

__global__ __launch_bounds__(NTHREADS) void setembed_epilogue(
    const int* __restrict__ setSizes,
    const float* __restrict__ W2, const float* __restrict__ b2,
    const float* __restrict__ W3, const float* __restrict__ b3,
    float* __restrict__ out)
{
    const int b = blockIdx.x * NTHREADS + threadIdx.x;   // one batch per thread
    const float4* sp = reinterpret_cast<const float4*>(
        &g_scratch[b * NTILES * K1]);
    float accs[K1];
#pragma unroll
    for (int q = 0; q < 4; q++) {                        // k-quad q
        float4 v0 = sp[q], v1 = sp[4 + q], v2 = sp[8 + q], v3 = sp[12 + q];
        accs[4 * q + 0] = (v0.x + v1.x) + (v2.x + v3.x);
        accs[4 * q + 1] = (v0.y + v1.y) + (v2.y + v3.y);
        accs[4 * q + 2] = (v0.z + v1.z) + (v2.z + v3.z);
        accs[4 * q + 3] = (v0.w + v1.w) + (v2.w + v3.w);
    }
    const float fn = (float)setSizes[b];
    float pooled[K2];
#pragma unroll
    for (int j = 0; j < K2; j++) {
        float p = fn * b2[j];                            // mask-summed b2 term
#pragma unroll
        for (int kk = 0; kk < K1; kk++) p += accs[kk] * W2[kk * K2 + j];
        pooled[j] = p;
    }
#pragma unroll
    for (int o = 0; o < NOUT; o++) {
        float v = b3[o];
#pragma unroll
        for (int m = 0; m < K2; m++) v += pooled[m] * W3[m * NOUT + o];
        out[(size_t)b * NOUT + o] = v;
    }
}

extern "C" void kernel_launch(void* const* d_in, const int* in_sizes, int n_in,
                              void* d_out, int out_size)
{
    const float* X  = (const float*)d_in[0];
    const int*   ss = (const int*)  d_in[1];
    const float* W1 = (const float*)d_in[2];
    const float* b1 = (const float*)d_in[3];
    const float* W2 = (const float*)d_in[4];
    const float* b2 = (const float*)d_in[5];
    const float* W3 = (const float*)d_in[6];
    const float* b3 = (const float*)d_in[7];
    float* o = (float*)d_out;
    setembed_main<<<B_ * NTILES, NTHREADS>>>(X, ss, W1, b1);
    setembed_epilogue<<<B_ / NTHREADS, NTHREADS>>>(ss, W2, b2, W3, b3, o);
}